// round 2
// baseline (speedup 1.0000x reference)
#include <cuda_runtime.h>
#include <cuda_bf16.h>

// loss = 2.0 - 2.0 * (sum_i feature[i, label[i]] / 64.0) / n
//      = 2.0 - sum_i feature[i, label[i]] / (32.0 * n)
//
// Only 8192 gathered fp32 values matter (one per row). Two graph nodes:
//   kernel 1: d_out[0] = 2.0f
//   kernel 2: one thread per row gathers feature[i*C + label[i]],
//             block-reduce, one atomicAdd(-partial/(32n)) per block.
//
// NOTE: label is int32 on device (JAX x64 disabled downcasts the declared
// int64), per the harness dtype table. Reading it as int64 was the R1 fault.

__global__ void center_init_kernel(float* out) {
    out[0] = 2.0f;
}

__global__ void center_gather_kernel(const float* __restrict__ feature,
                                     const int* __restrict__ label,
                                     float* __restrict__ out,
                                     int n, int num_classes, float inv_scale_n) {
    int i = blockIdx.x * blockDim.x + threadIdx.x;
    float v = 0.0f;
    if (i < n) {
        int col = label[i];
        // defensive clamp (free; wrong dtype would still fail rel-err check)
        col = min(max(col, 0), num_classes - 1);
        v = __ldg(&feature[(size_t)i * (size_t)num_classes + (size_t)col]);
    }

    // warp reduce
    #pragma unroll
    for (int off = 16; off > 0; off >>= 1)
        v += __shfl_down_sync(0xFFFFFFFFu, v, off);

    __shared__ float warp_sums[8];
    int lane = threadIdx.x & 31;
    int wid  = threadIdx.x >> 5;
    if (lane == 0) warp_sums[wid] = v;
    __syncthreads();

    if (wid == 0) {
        int nwarps = (blockDim.x + 31) >> 5;
        v = (lane < nwarps) ? warp_sums[lane] : 0.0f;
        #pragma unroll
        for (int off = 4; off > 0; off >>= 1)
            v += __shfl_down_sync(0xFFFFFFFFu, v, off);
        if (lane == 0)
            atomicAdd(out, -v * inv_scale_n);
    }
}

extern "C" void kernel_launch(void* const* d_in, const int* in_sizes, int n_in,
                              void* d_out, int out_size) {
    const float* feature = (const float*)d_in[0];
    const int*   label   = (const int*)d_in[1];
    float*       out     = (float*)d_out;

    int n = in_sizes[1];                  // 8192 labels
    int num_classes = in_sizes[0] / n;    // 10000

    // loss = 2 - sum / (32 * n)
    float inv_scale_n = 1.0f / (32.0f * (float)n);

    center_init_kernel<<<1, 1>>>(out);

    int threads = 256;
    int blocks = (n + threads - 1) / threads;   // 32 blocks
    center_gather_kernel<<<blocks, threads>>>(feature, label, out,
                                              n, num_classes, inv_scale_n);
}

// round 3
// speedup vs baseline: 1.1643x; 1.1643x over previous
#include <cuda_runtime.h>
#include <cuda_bf16.h>

// loss = 2.0 - sum_i feature[i, label[i]] / (32.0 * n)
//
// Single fused kernel (one graph node):
//   - each thread gathers feature[i*C + label[i]]
//   - block reduce (shfl + smem)
//   - block partial atomicAdd'ed into __device__ g_partial
//   - last finished block (ticket counter) reads total via atomicExch
//     (which also resets the accumulator for the next graph replay),
//     writes out[0] = 2 - total/(32n), and resets the ticket.
// Device globals are statically zero-initialized and restored to zero at the
// end of every launch -> deterministic across correctness run and replays.

__device__ float        g_partial = 0.0f;
__device__ unsigned int g_ticket  = 0u;

__global__ void center_fused_kernel(const float* __restrict__ feature,
                                    const int* __restrict__ label,
                                    float* __restrict__ out,
                                    int n, int num_classes, float inv_scale_n) {
    int i = blockIdx.x * blockDim.x + threadIdx.x;
    float v = 0.0f;
    if (i < n) {
        int col = label[i];
        col = min(max(col, 0), num_classes - 1);   // defensive, ~free
        v = __ldg(&feature[(size_t)i * (size_t)num_classes + (size_t)col]);
    }

    // intra-warp reduce
    #pragma unroll
    for (int off = 16; off > 0; off >>= 1)
        v += __shfl_down_sync(0xFFFFFFFFu, v, off);

    __shared__ float warp_sums[8];
    int lane = threadIdx.x & 31;
    int wid  = threadIdx.x >> 5;
    if (lane == 0) warp_sums[wid] = v;
    __syncthreads();

    if (wid == 0) {
        int nwarps = (blockDim.x + 31) >> 5;
        v = (lane < nwarps) ? warp_sums[lane] : 0.0f;
        #pragma unroll
        for (int off = 4; off > 0; off >>= 1)
            v += __shfl_down_sync(0xFFFFFFFFu, v, off);

        if (lane == 0) {
            atomicAdd(&g_partial, v);
            __threadfence();                       // partial visible before ticket
            unsigned int t = atomicAdd(&g_ticket, 1u);
            if (t == gridDim.x - 1) {
                // all partials (incl. ours) are in; read + reset in one op
                float total = atomicExch(&g_partial, 0.0f);
                out[0] = 2.0f - total * inv_scale_n;
                atomicExch(&g_ticket, 0u);         // reset for next replay
            }
        }
    }
}

extern "C" void kernel_launch(void* const* d_in, const int* in_sizes, int n_in,
                              void* d_out, int out_size) {
    const float* feature = (const float*)d_in[0];
    const int*   label   = (const int*)d_in[1];
    float*       out     = (float*)d_out;

    int n = in_sizes[1];                  // 8192 labels
    int num_classes = in_sizes[0] / n;    // 10000

    float inv_scale_n = 1.0f / (32.0f * (float)n);

    int threads = 256;
    int blocks  = (n + threads - 1) / threads;   // 32 blocks
    center_fused_kernel<<<blocks, threads>>>(feature, label, out,
                                             n, num_classes, inv_scale_n);
}